// round 4
// baseline (speedup 1.0000x reference)
#include <cuda_runtime.h>

#define G 1024
#define RPT 4        // rows per thread
#define NBLOCKS 512  // grid 16 x 32, block 32x8, each thread: 2 cols x 4 rows

__device__ float2 g_part[NBLOCKS];
__device__ unsigned int g_cnt = 0;

#define C11 (1.0f / 0.91f)
#define C12 (0.3f / 0.91f)
#define C33 (0.35f / 0.91f)
#define A2c (2.0f * (C11 + C33))
#define BGc (0.5f * (C12 + C33))

struct RowW { float2 c0, c1, c2, c3; };  // cols j-1, j, j+1, j+2 (clamped)
struct TRow { float2 a, b, c; };         // ut cols j, j+1, j+2 (clamped)

__device__ __forceinline__ float4 ldf4(const float2* __restrict__ p, int i, int jc) {
    return __ldg(reinterpret_cast<const float4*>(p + i * G + jc));
}

__device__ __forceinline__ RowW load_row(const float2* __restrict__ p, int i,
                                         int j, int jA, int jC, bool lft, bool rgt) {
    float4 A = ldf4(p, i, jA);   // jA = max(j-2,0):  cols {jA, jA+1}
    float4 B = ldf4(p, i, j);    // cols {j, j+1}
    float4 C = ldf4(p, i, jC);   // jC = min(j+2,G-2): cols {jC, jC+1}
    RowW w;
    w.c0 = lft ? make_float2(A.x, A.y) : make_float2(A.z, A.w);  // col max(j-1,0)
    w.c1 = make_float2(B.x, B.y);
    w.c2 = make_float2(B.z, B.w);
    w.c3 = rgt ? make_float2(C.z, C.w) : make_float2(C.x, C.y);  // col min(j+2,G-1)
    return w;
}

__device__ __forceinline__ TRow load_trow(const float2* __restrict__ p, int i,
                                          int j, int jC, bool rgt) {
    float4 B = ldf4(p, i, j);
    float4 C = ldf4(p, i, jC);
    TRow t;
    t.a = make_float2(B.x, B.y);
    t.b = make_float2(B.z, B.w);
    t.c = rgt ? make_float2(C.z, C.w) : make_float2(C.x, C.y);  // masked when rgt
    return t;
}

// tri1 (corners a, b=a+j, c=a+i): s = C * d
#define TRI1(s0, s1, s2, ua, ub, uc)                                        \
    {                                                                       \
        float d0 = (uc).x - (ua).x;                                         \
        float d1 = (ub).y - (ua).y;                                         \
        float d2 = (ub).x + (uc).y - (ua).x - (ua).y;                       \
        s0 = C11 * d0 + C12 * d1;                                           \
        s1 = C12 * d0 + C11 * d1;                                           \
        s2 = C33 * d2;                                                      \
    }
// tri2 (corners b, d=b+i, c=d-j)
#define TRI2(t0, t1, t2, ub, ud, uc)                                        \
    {                                                                       \
        float e0 = (ud).x - (ub).x;                                         \
        float e1 = (ud).y - (uc).y;                                         \
        float e2 = (ud).x + (ud).y - (ub).y - (uc).x;                       \
        t0 = C11 * e0 + C12 * e1;                                           \
        t1 = C12 * e0 + C11 * e1;                                           \
        t2 = C33 * e2;                                                      \
    }

// residual at node (i, jc); window rows are clamped, j-clamp is baked into the cols
__device__ __forceinline__ void node_R(
    float2 u01, float2 u02,
    float2 u10, float2 u11, float2 u12,
    float2 u20, float2 u21,
    bool interior, int i, int jc, float& Rx, float& Ry) {
    if (interior) {
        float Vx = u01.x + u21.x, Hx = u10.x + u12.x;
        float Vy = u01.y + u21.y, Hy = u10.y + u12.y;
        float Tx = 2.f * u11.x - Vx - Hx + u20.x + u02.x;
        float Ty = 2.f * u11.y - Vy - Hy + u20.y + u02.y;
        Rx = A2c * u11.x - C11 * Vx - C33 * Hx + BGc * Ty;
        Ry = A2c * u11.y - C11 * Hy - C33 * Vy + BGc * Tx;
    } else {
        const float mA = (i < G - 1 && jc < G - 1) ? 1.f : 0.f;
        const float mB = (i < G - 1 && jc > 0) ? 1.f : 0.f;
        const float mC = (i > 0 && jc < G - 1) ? 1.f : 0.f;
        const float mD = (i > 0 && jc > 0) ? 1.f : 0.f;
        float sA0, sA1, sA2; TRI1(sA0, sA1, sA2, u11, u12, u21);
        float sB0, sB1, sB2; TRI1(sB0, sB1, sB2, u10, u11, u20);
        float tB0, tB1, tB2; TRI2(tB0, tB1, tB2, u11, u21, u20);
        float sC0, sC1, sC2; TRI1(sC0, sC1, sC2, u01, u02, u11);
        float tC0, tC1, tC2; TRI2(tC0, tC1, tC2, u02, u12, u11);
        float tD0, tD1, tD2; TRI2(tD0, tD1, tD2, u01, u11, u10);
        (void)sB0; (void)tB1; (void)sC1; (void)tC0;
        Rx = mA * (-0.5f) * (sA0 + sA2) + mB * 0.5f * (sB2 - tB0) +
             mC * 0.5f * (sC0 - tC2)    + mD * 0.5f * (tD0 + tD2);
        Ry = mA * (-0.5f) * (sA1 + sA2) + mB * 0.5f * (sB1 - tB2) +
             mC * 0.5f * (sC2 - tC1)    + mD * 0.5f * (tD1 + tD2);
    }
}

// energy of one cell with error corners a=(i,j) b=(i,j+1) c=(i+1,j) d=(i+1,j+1)
__device__ __forceinline__ float cell_E(float2 a, float2 b, float2 c, float2 d) {
    float d0 = c.x - a.x, d1 = b.y - a.y, d2 = b.x + c.y - a.x - a.y;
    float e0 = d.x - b.x, e1 = d.y - c.y, e2 = d.x + d.y - b.y - c.x;
    return C11 * (d0 * d0 + d1 * d1) + 2.f * C12 * (d0 * d1) + C33 * (d2 * d2) +
           C11 * (e0 * e0 + e1 * e1) + 2.f * C12 * (e0 * e1) + C33 * (e2 * e2);
}

__global__ __launch_bounds__(256, 3) void pino_fused_kernel(
    const float2* __restrict__ up, const float2* __restrict__ ut,
    float* __restrict__ out) {
    const int j = (blockIdx.x * 32 + threadIdx.x) * 2;          // even col, 0..1022
    const int i0 = (blockIdx.y * 8 + threadIdx.y) * RPT;
    const bool lft = (j == 0), rgt = (j == G - 2);
    const int jA = max(j - 2, 0), jC = min(j + 2, G - 2);

    const int rm = max(i0 - 1, 0);
    RowW wm = load_row(up, rm, j, jA, jC, lft, rgt);
    RowW wc = load_row(up, i0, j, jA, jC, lft, rgt);
    RowW wn = load_row(up, i0 + 1, j, jA, jC, lft, rgt);
    TRow tc = load_trow(ut, i0, j, jC, rgt);

    float vr = 0.f, ve = 0.f;

    #pragma unroll
    for (int k = 0; k < RPT; k++) {
        const int i = i0 + k;
        TRow tn = load_trow(ut, min(i + 1, G - 1), j, jC, rgt);

        const bool iint = (i > 0) && (i < G - 1);
        float RxA, RyA, RxB, RyB;
        // node A: col j, window cols (c0,c1,c2)
        node_R(wm.c1, wm.c2, wc.c0, wc.c1, wc.c2, wn.c0, wn.c1,
               iint && (j > 0), i, j, RxA, RyA);
        // node B: col j+1, window cols (c1,c2,c3)
        node_R(wm.c2, wm.c3, wc.c1, wc.c2, wc.c3, wn.c1, wn.c2,
               iint && !rgt, i, j + 1, RxB, RyB);
        vr += RxA * RxA + RyA * RyA + RxB * RxB + RyB * RyB;

        // energy of cells (i,j) and (i,j+1) on u_err (x0.5 at final combine)
        if (i < G - 1) {
            float2 E10 = make_float2(wc.c1.x - tc.a.x, wc.c1.y - tc.a.y);
            float2 E11 = make_float2(wc.c2.x - tc.b.x, wc.c2.y - tc.b.y);
            float2 E20 = make_float2(wn.c1.x - tn.a.x, wn.c1.y - tn.a.y);
            float2 E21 = make_float2(wn.c2.x - tn.b.x, wn.c2.y - tn.b.y);
            ve += cell_E(E10, E11, E20, E21);
            if (!rgt) {
                float2 E12 = make_float2(wc.c3.x - tc.c.x, wc.c3.y - tc.c.y);
                float2 E22 = make_float2(wn.c3.x - tn.c.x, wn.c3.y - tn.c.y);
                ve += cell_E(E11, E12, E21, E22);
            }
        }

        // roll window down one row
        wm = wc; wc = wn;
        if (k < RPT - 1) wn = load_row(up, min(i + 2, G - 1), j, jA, jC, lft, rgt);
        tc = tn;
    }

    // ---- block reduction ----
    #pragma unroll
    for (int o = 16; o; o >>= 1) {
        vr += __shfl_down_sync(0xFFFFFFFFu, vr, o);
        ve += __shfl_down_sync(0xFFFFFFFFu, ve, o);
    }
    __shared__ float sr[8], se[8];
    __shared__ unsigned s_last;
    if (threadIdx.x == 0) { sr[threadIdx.y] = vr; se[threadIdx.y] = ve; }
    __syncthreads();
    if (threadIdx.x == 0 && threadIdx.y == 0) {
        float a = 0.f, b = 0.f;
        #pragma unroll
        for (int q = 0; q < 8; q++) { a += sr[q]; b += se[q]; }
        int bid = blockIdx.y * gridDim.x + blockIdx.x;
        g_part[bid] = make_float2(a, b);
        __threadfence();
        unsigned old = atomicAdd(&g_cnt, 1u);
        s_last = (old == NBLOCKS - 1) ? 1u : 0u;
    }
    __syncthreads();

    // ---- last block finishes (fixed order -> deterministic) ----
    if (s_last) {
        const int t = threadIdx.y * 32 + threadIdx.x;
        double a = 0.0, b = 0.0;
        #pragma unroll
        for (int q = 0; q < NBLOCKS / 256; q++) {
            float2 v = g_part[q * 256 + t];
            a += (double)v.x;
            b += (double)v.y;
        }
        #pragma unroll
        for (int o = 16; o; o >>= 1) {
            a += __shfl_down_sync(0xFFFFFFFFu, a, o);
            b += __shfl_down_sync(0xFFFFFFFFu, b, o);
        }
        __shared__ double dr[8], de[8];
        if ((t & 31) == 0) { dr[t >> 5] = a; de[t >> 5] = b; }
        __syncthreads();
        if (t == 0) {
            double ta = 0.0, tb = 0.0;
            #pragma unroll
            for (int q = 0; q < 8; q++) { ta += dr[q]; tb += de[q]; }
            double leq = ta / (2.0 * (double)G * (double)G);  // mean(R^2)
            double len = 0.5 * tb;  // total_area telescopes to 1.0
            out[0] = (float)(0.1 * leq + 0.1 * len);
            g_cnt = 0;  // reset for next graph replay
        }
    }
}

extern "C" void kernel_launch(void* const* d_in, const int* in_sizes, int n_in,
                              void* d_out, int out_size) {
    const float2* up = (const float2*)d_in[0];  // u_pred (N,2)
    const float2* ut = (const float2*)d_in[1];  // u_true (N,2)
    (void)in_sizes; (void)n_in; (void)out_size;

    dim3 blk(32, 8);
    dim3 grd(G / 64, G / (8 * RPT));  // 16 x 32 = 512 blocks
    pino_fused_kernel<<<grd, blk>>>(up, ut, (float*)d_out);
}